// round 3
// baseline (speedup 1.0000x reference)
#include <cuda_runtime.h>
#include <cuda_bf16.h>
#include <cstdint>

typedef unsigned long long ull;

#define B_    64
#define T_    2048
#define H_    512
#define G_    2048      // 4*H
#define NCTA  128       // persistent CTAs, each owns 4 h-cols = 16 gate cols
#define CPC   16        // gate cols per CTA

// ---------------- device scratch (static, allowed) ----------------
__device__ __align__(16) float  g_xg[(size_t)T_ * G_ * B_];      // 1 GiB  [t][pcol][b]
__device__ __align__(16) float  g_hs[(size_t)T_ * H_ * B_];      // 256 MB [t][k][b]
__device__ __align__(16) float2 g_whdup[NCTA * H_ * CPC];        // 8 MB, duplicated W_h, permuted
__device__ __align__(16) float  g_bossT[G_ * 64];                // [pcol][vocab(pad64)]
__device__ __align__(16) float  g_heroT[G_ * 200];               // [pcol][vocab200]
__device__ __align__(16) float4 g_cwb[G_];                       // (Wc0,Wc1,Wc2,bias) permuted
__device__ __align__(16) float  g_hbuf[2][H_ * B_];              // double-buffered h [k][b]
__device__ unsigned g_bar;

// ---------------- helpers ----------------
__device__ __forceinline__ ull pk2(float x, float y) {
    ull r; asm("mov.b64 %0, {%1,%2};" : "=l"(r) : "f"(x), "f"(y)); return r;
}
__device__ __forceinline__ float2 upk(ull v) {
    float2 f; asm("mov.b64 {%0,%1}, %2;" : "=f"(f.x), "=f"(f.y) : "l"(v)); return f;
}
__device__ __forceinline__ void fma2(ull& d, ull a, ull b) {
    asm("fma.rn.f32x2 %0, %1, %2, %3;" : "=l"(d) : "l"(a), "l"(b), "l"(d));
}
__device__ __forceinline__ void cp16(uint32_t s, const void* g) {
    asm volatile("cp.async.cg.shared.global [%0], [%1], 16;" :: "r"(s), "l"(g) : "memory");
}
__device__ __forceinline__ void cpcommit() { asm volatile("cp.async.commit_group;" ::: "memory"); }
template <int N> __device__ __forceinline__ void cpwait() {
    asm volatile("cp.async.wait_group %0;" :: "n"(N) : "memory");
}
__device__ __forceinline__ float sigf(float x) { return 1.0f / (1.0f + __expf(-x)); }

// permutation: pcol = cta*16 + gate*4 + j  <->  orig gate col = gate*512 + cta*4 + j
__device__ __forceinline__ int orig_col(int pcol) {
    int cta = pcol >> 4, r = pcol & 15, gate = r >> 2, j = r & 3;
    return gate * H_ + cta * 4 + j;
}

// ---------------- kernel 0: init (reset barrier + h0) ----------------
__global__ void k_init() {
    int tid = threadIdx.x + blockIdx.x * blockDim.x;
    if (tid == 0) g_bar = 0u;
    for (int i = tid; i < H_ * B_; i += blockDim.x * gridDim.x) {
        g_hbuf[0][i] = 0.f;
        g_hbuf[1][i] = 0.f;
    }
}

// ---------------- kernel 1: projections + weight permute ----------------
// grid = 2048 (one block per pcol), 256 threads
__global__ void k_prep(const float* __restrict__ boss_table,
                       const float* __restrict__ hero_table,
                       const float* __restrict__ W_i,
                       const float* __restrict__ W_h,
                       const float* __restrict__ b_lstm) {
    int pcol = blockIdx.x;
    int o = orig_col(pcol);
    int tid = threadIdx.x;

    if (tid < 50) {
        float s = 0.f;
        #pragma unroll
        for (int e = 0; e < 32; ++e) s += boss_table[tid * 32 + e] * W_i[e * G_ + o];
        g_bossT[pcol * 64 + tid] = s;
    } else if (tid < 250) {
        int v = tid - 50;
        float s = 0.f;
        #pragma unroll
        for (int e = 0; e < 32; ++e) s += hero_table[v * 32 + e] * W_i[(32 + e) * G_ + o];
        g_heroT[pcol * 200 + v] = s;
    } else if (tid == 250) {
        g_cwb[pcol] = make_float4(W_i[64 * G_ + o], W_i[65 * G_ + o], W_i[66 * G_ + o], b_lstm[o]);
    }
    // duplicated, permuted W_h slice: whdup[cta][k][localc]
    int cta = pcol >> 4, r = pcol & 15;
    for (int k = tid; k < H_; k += 256) {
        float w = W_h[k * G_ + o];
        g_whdup[(cta * H_ + k) * CPC + r] = make_float2(w, w);
    }
}

// ---------------- kernel 2: build xg[t][pcol][b] ----------------
// grid = 2048 (one block per t), 256 threads
__global__ void k_xg(const int* __restrict__ boss_anim,
                     const int* __restrict__ hero_anim,
                     const float* __restrict__ cont) {
    __shared__ int   sb[B_], sh[B_];
    __shared__ float sc[B_][3];
    int t = blockIdx.x, tid = threadIdx.x;
    if (tid < B_) {
        int b = tid;
        int bi = boss_anim[b * T_ + t]; bi = min(max(bi, 0), 49);
        int hi = hero_anim[b * T_ + t]; hi = min(max(hi, 0), 199);
        sb[b] = bi; sh[b] = hi;
        size_t cb = ((size_t)b * T_ + t) * 3;
        sc[b][0] = cont[cb + 0]; sc[b][1] = cont[cb + 1]; sc[b][2] = cont[cb + 2];
    }
    __syncthreads();
    size_t base = (size_t)t * G_ * B_;
    for (int idx = tid; idx < G_ * B_; idx += 256) {
        int b = idx & 63;
        int pcol = idx >> 6;
        float4 w = g_cwb[pcol];
        float v = g_bossT[pcol * 64 + sb[b]] + g_heroT[pcol * 200 + sh[b]]
                + sc[b][0] * w.x + sc[b][1] * w.y + sc[b][2] * w.z + w.w;
        g_xg[base + idx] = v;
    }
}

// ---------------- kernel 3: persistent LSTM recurrence ----------------
// grid = 128, block = 256, dyn smem = 64KB(W) + 128KB(h) + 4KB(g)
__global__ void __launch_bounds__(256, 1) k_recur() {
    extern __shared__ char smem[];
    float2* whs = (float2*)smem;                       // [512][16] duplicated W
    float*  hsm = (float*)(smem + 65536);              // [512][64]
    float*  gsm = (float*)(smem + 65536 + 131072);     // [16][64]

    int cta = blockIdx.x, tid = threadIdx.x;

    // one-time: stage this CTA's W_h slice
    const float2* wsrc = g_whdup + (size_t)cta * H_ * CPC;
    for (int i = tid; i < H_ * CPC; i += 256) whs[i] = wsrc[i];

    // GEMM roles: thread = (btile, ctile) -> b pair {b0,b0+1}, cols {c0,c0+1}
    int btile = tid & 31, ctile = tid >> 5;
    int b0 = 2 * btile, c0 = 2 * ctile;
    // apply roles: thread = (j, b)
    int jj = tid >> 6, bb = tid & 63;
    float c_state = 0.f;

    const ulonglong2* wp = (const ulonglong2*)whs;     // [k*8 + ctile] -> {dup(wc0),dup(wc1)}
    const ull*        hp = (const ull*)hsm;            // [k*32 + btile]

    uint32_t hsm_s = (uint32_t)__cvta_generic_to_shared(hsm);
    __syncthreads();

    for (int t = 0; t < T_; ++t) {
        // acc init from xg (issue LDGs early)
        size_t xbase = (size_t)t * (G_ * B_) + (size_t)(cta * CPC) * B_;
        ull acc0 = *(const ull*)(g_xg + xbase + (size_t)c0 * B_ + b0);
        ull acc1 = *(const ull*)(g_xg + xbase + (size_t)(c0 + 1) * B_ + b0);

        // async-load h (4 k-chunks of 128)
        const float4* hsrc = (const float4*)g_hbuf[t & 1];
        #pragma unroll
        for (int ck = 0; ck < 4; ++ck) {
            #pragma unroll
            for (int i = 0; i < 8; ++i) {
                int e4 = ck * 2048 + (i << 8) + tid;
                cp16(hsm_s + e4 * 16, hsrc + e4);
            }
            cpcommit();
        }

        #define COMP_CHUNK(CK, NW)                                            \
        {                                                                     \
            cpwait<NW>();                                                     \
            __syncthreads();                                                  \
            _Pragma("unroll 8")                                               \
            for (int k = (CK) * 128; k < (CK) * 128 + 128; ++k) {             \
                ull h2 = hp[k * 32 + btile];                                  \
                ulonglong2 wv = wp[k * 8 + ctile];                            \
                fma2(acc0, h2, wv.x);                                         \
                fma2(acc1, h2, wv.y);                                         \
            }                                                                 \
        }
        COMP_CHUNK(0, 3)
        COMP_CHUNK(1, 2)
        COMP_CHUNK(2, 1)
        COMP_CHUNK(3, 0)
        #undef COMP_CHUNK

        // stage gates
        *(float2*)&gsm[c0 * B_ + b0]       = upk(acc0);
        *(float2*)&gsm[(c0 + 1) * B_ + b0] = upk(acc1);
        __syncthreads();

        // gate nonlinearity + state update (thread owns h-col cta*4+jj, batch bb)
        float gi = gsm[(0 * 4 + jj) * B_ + bb];
        float gf = gsm[(1 * 4 + jj) * B_ + bb];
        float gg = gsm[(2 * 4 + jj) * B_ + bb];
        float go = gsm[(3 * 4 + jj) * B_ + bb];
        float iv = sigf(gi), fv = sigf(gf), gv = tanhf(gg), ov = sigf(go);
        c_state = fv * c_state + iv * gv;
        float h = ov * tanhf(c_state);
        int hc = cta * 4 + jj;
        g_hbuf[(t + 1) & 1][hc * B_ + bb] = h;
        g_hs[(size_t)t * (H_ * B_) + hc * B_ + bb] = h;

        // grid barrier (monotone counter; reset each launch by k_init)
        __threadfence();
        __syncthreads();
        if (tid == 0) {
            atomicAdd(&g_bar, 1u);
            unsigned tgt = (unsigned)NCTA * (unsigned)(t + 1);
            while (*(volatile unsigned*)&g_bar < tgt) { }
            __threadfence();
        }
        __syncthreads();
    }
}

// ---------------- kernel 4: MLP epilogue ----------------
// grid = 2048 (one block per t), 256 threads
// out[b][t] = relu(hs[b,t,:]@W1 + b1) @ W2 + b2
__global__ void __launch_bounds__(256, 1) k_mlp(const float* __restrict__ W1,
                                                const float* __restrict__ b1,
                                                const float* __restrict__ W2,
                                                const float* __restrict__ b2,
                                                float* __restrict__ out) {
    extern __shared__ char smem[];
    float* hsm = (float*)smem;                          // [512][64] 128KB
    float* w1c = (float*)(smem + 131072);               // [64][256] 64KB
    float* b1s = (float*)(smem + 131072 + 65536);       // 256
    float* w2s = b1s + 256;                             // 256
    float* red = w2s + 256;                             // [16][64]

    int t = blockIdx.x, tid = threadIdx.x;

    const float4* hsrc = (const float4*)(g_hs + (size_t)t * (H_ * B_));
    float4* hd = (float4*)hsm;
    for (int i = tid; i < H_ * B_ / 4; i += 256) hd[i] = hsrc[i];
    b1s[tid] = b1[tid];
    w2s[tid] = W2[tid];
    __syncthreads();

    // thread tile: 4 b x 16 m
    int bt = tid & 15, mt = tid >> 4;
    int b0 = bt * 4, m0 = mt * 16;

    ull acc[16][2];
    #pragma unroll
    for (int m = 0; m < 16; ++m) {
        float bv = b1s[m0 + m];
        acc[m][0] = pk2(bv, bv);
        acc[m][1] = pk2(bv, bv);
    }

    for (int kc = 0; kc < 8; ++kc) {
        if (kc > 0) __syncthreads();
        const float4* wsrc = (const float4*)(W1 + (size_t)kc * 64 * 256);
        for (int i = tid; i < 4096; i += 256) ((float4*)w1c)[i] = wsrc[i];
        __syncthreads();
        #pragma unroll 4
        for (int k = 0; k < 64; ++k) {
            const ull* hp = (const ull*)&hsm[(kc * 64 + k) * B_ + b0];
            ull h01 = hp[0], h23 = hp[1];
            const float* wr = &w1c[k * 256 + m0];
            #pragma unroll
            for (int m4 = 0; m4 < 4; ++m4) {
                float4 w = *(const float4*)&wr[m4 * 4];
                ull wa = pk2(w.x, w.x), wb = pk2(w.y, w.y);
                ull wc = pk2(w.z, w.z), wd = pk2(w.w, w.w);
                fma2(acc[m4 * 4 + 0][0], h01, wa); fma2(acc[m4 * 4 + 0][1], h23, wa);
                fma2(acc[m4 * 4 + 1][0], h01, wb); fma2(acc[m4 * 4 + 1][1], h23, wb);
                fma2(acc[m4 * 4 + 2][0], h01, wc); fma2(acc[m4 * 4 + 2][1], h23, wc);
                fma2(acc[m4 * 4 + 3][0], h01, wd); fma2(acc[m4 * 4 + 3][1], h23, wd);
            }
        }
    }

    // relu + dot with W2 (partial over this thread's 16 m)
    float p0 = 0.f, p1 = 0.f, p2 = 0.f, p3 = 0.f;
    #pragma unroll
    for (int m = 0; m < 16; ++m) {
        float2 v0 = upk(acc[m][0]), v1 = upk(acc[m][1]);
        float wv = w2s[m0 + m];
        p0 += fmaxf(v0.x, 0.f) * wv;
        p1 += fmaxf(v0.y, 0.f) * wv;
        p2 += fmaxf(v1.x, 0.f) * wv;
        p3 += fmaxf(v1.y, 0.f) * wv;
    }
    red[mt * B_ + b0 + 0] = p0;
    red[mt * B_ + b0 + 1] = p1;
    red[mt * B_ + b0 + 2] = p2;
    red[mt * B_ + b0 + 3] = p3;
    __syncthreads();
    if (tid < B_) {
        float s = b2[0];
        #pragma unroll
        for (int q = 0; q < 16; ++q) s += red[q * B_ + tid];
        out[(size_t)tid * T_ + t] = s;
    }
}

// ---------------- launch ----------------
extern "C" void kernel_launch(void* const* d_in, const int* in_sizes, int n_in,
                              void* d_out, int out_size) {
    const int*   boss_anim  = (const int*)d_in[0];
    const int*   hero_anim  = (const int*)d_in[1];
    const float* continuous = (const float*)d_in[2];
    const float* boss_table = (const float*)d_in[3];
    const float* hero_table = (const float*)d_in[4];
    const float* W_i        = (const float*)d_in[5];
    const float* W_h        = (const float*)d_in[6];
    const float* b_lstm     = (const float*)d_in[7];
    const float* W1         = (const float*)d_in[8];
    const float* b1         = (const float*)d_in[9];
    const float* W2         = (const float*)d_in[10];
    const float* b2         = (const float*)d_in[11];
    float* out = (float*)d_out;

    static bool attr_done = false;
    if (!attr_done) {
        cudaFuncSetAttribute(k_recur, cudaFuncAttributeMaxDynamicSharedMemorySize, 65536 + 131072 + 4096);
        cudaFuncSetAttribute(k_mlp,   cudaFuncAttributeMaxDynamicSharedMemorySize, 131072 + 65536 + 2048 + 4096);
        attr_done = true;
    }

    k_init<<<32, 256>>>();
    k_prep<<<G_, 256>>>(boss_table, hero_table, W_i, W_h, b_lstm);
    k_xg<<<T_, 256>>>(boss_anim, hero_anim, continuous);
    k_recur<<<NCTA, 256, 65536 + 131072 + 4096>>>();
    k_mlp<<<T_, 256, 131072 + 65536 + 2048 + 4096>>>(W1, b1, W2, b2, out);
}

// round 4
// speedup vs baseline: 1.6196x; 1.6196x over previous
#include <cuda_runtime.h>
#include <cuda_bf16.h>
#include <cstdint>

typedef unsigned long long ull;

#define B_    64
#define T_    2048
#define H_    512
#define G_    2048      // 4*H
#define NCTA  128       // persistent CTAs, each owns 4 h-cols = 16 gate cols
#define CPC   16        // gate cols per CTA

// ---------------- device scratch (static, allowed) ----------------
__device__ __align__(16) float  g_xg[(size_t)T_ * G_ * B_];      // 1 GiB  [t][pcol][b]
__device__ __align__(16) float  g_hs[(size_t)T_ * H_ * B_];      // 256 MB [t][k][b] natural
__device__ __align__(16) float2 g_whdup[NCTA * H_ * CPC];        // 8 MB, duplicated W_h, permuted
__device__ __align__(16) float  g_bossT[G_ * 64];                // [pcol][vocab(pad64)]
__device__ __align__(16) float  g_heroT[G_ * 200];               // [pcol][vocab200]
__device__ __align__(16) float4 g_cwb[G_];                       // (Wc0,Wc1,Wc2,bias) permuted
__device__ __align__(16) float  g_hbuf[2][H_ * B_];              // double-buffered h [k][permuted b]
__device__ unsigned g_bar;

// ---------------- helpers ----------------
__device__ __forceinline__ ull pk2(float x, float y) {
    ull r; asm("mov.b64 %0, {%1,%2};" : "=l"(r) : "f"(x), "f"(y)); return r;
}
__device__ __forceinline__ float2 upk(ull v) {
    float2 f; asm("mov.b64 {%0,%1}, %2;" : "=f"(f.x), "=f"(f.y) : "l"(v)); return f;
}
__device__ __forceinline__ void fma2(ull& d, ull a, ull b) {
    asm("fma.rn.f32x2 %0, %1, %2, %3;" : "=l"(d) : "l"(a), "l"(b), "l"(d));
}
__device__ __forceinline__ void add2(ull& d, ull a) {
    asm("add.rn.f32x2 %0, %1, %2;" : "=l"(d) : "l"(d), "l"(a));
}
__device__ __forceinline__ void cp16(uint32_t s, const void* g) {
    asm volatile("cp.async.cg.shared.global [%0], [%1], 16;" :: "r"(s), "l"(g) : "memory");
}
__device__ __forceinline__ void cpcommit() { asm volatile("cp.async.commit_group;" ::: "memory"); }
template <int N> __device__ __forceinline__ void cpwait() {
    asm volatile("cp.async.wait_group %0;" :: "n"(N) : "memory");
}
__device__ __forceinline__ float sigf(float x) { return 1.0f / (1.0f + __expf(-x)); }

// b-permutation for h rows (bank-conflict-free GEMM loads):
// 16B unit q = b>>2 placed at position (q&1)*8 + (q>>1)
__device__ __forceinline__ int permb(int b) {
    int q = b >> 2;
    return (((q & 1) * 8) + (q >> 1)) * 4 + (b & 3);
}

// permutation: pcol = cta*16 + gate*4 + j  <->  orig gate col = gate*512 + cta*4 + j
__device__ __forceinline__ int orig_col(int pcol) {
    int cta = pcol >> 4, r = pcol & 15, gate = r >> 2, j = r & 3;
    return gate * H_ + cta * 4 + j;
}

// ---------------- kernel 0: init (reset barrier + h0) ----------------
__global__ void k_init() {
    int tid = threadIdx.x + blockIdx.x * blockDim.x;
    if (tid == 0) g_bar = 0u;
    for (int i = tid; i < H_ * B_; i += blockDim.x * gridDim.x) {
        g_hbuf[0][i] = 0.f;
        g_hbuf[1][i] = 0.f;
    }
}

// ---------------- kernel 1: projections + weight permute ----------------
__global__ void k_prep(const float* __restrict__ boss_table,
                       const float* __restrict__ hero_table,
                       const float* __restrict__ W_i,
                       const float* __restrict__ W_h,
                       const float* __restrict__ b_lstm) {
    int pcol = blockIdx.x;
    int o = orig_col(pcol);
    int tid = threadIdx.x;

    if (tid < 50) {
        float s = 0.f;
        #pragma unroll
        for (int e = 0; e < 32; ++e) s += boss_table[tid * 32 + e] * W_i[e * G_ + o];
        g_bossT[pcol * 64 + tid] = s;
    } else if (tid < 250) {
        int v = tid - 50;
        float s = 0.f;
        #pragma unroll
        for (int e = 0; e < 32; ++e) s += hero_table[v * 32 + e] * W_i[(32 + e) * G_ + o];
        g_heroT[pcol * 200 + v] = s;
    } else if (tid == 250) {
        g_cwb[pcol] = make_float4(W_i[64 * G_ + o], W_i[65 * G_ + o], W_i[66 * G_ + o], b_lstm[o]);
    }
    int cta = pcol >> 4, r = pcol & 15;
    for (int k = tid; k < H_; k += 256) {
        float w = W_h[k * G_ + o];
        g_whdup[(cta * H_ + k) * CPC + r] = make_float2(w, w);
    }
}

// ---------------- kernel 2: build xg[t][pcol][b] ----------------
__global__ void k_xg(const int* __restrict__ boss_anim,
                     const int* __restrict__ hero_anim,
                     const float* __restrict__ cont) {
    __shared__ int   sb[B_], sh[B_];
    __shared__ float sc[B_][3];
    int t = blockIdx.x, tid = threadIdx.x;
    if (tid < B_) {
        int b = tid;
        int bi = boss_anim[b * T_ + t]; bi = min(max(bi, 0), 49);
        int hi = hero_anim[b * T_ + t]; hi = min(max(hi, 0), 199);
        sb[b] = bi; sh[b] = hi;
        size_t cb = ((size_t)b * T_ + t) * 3;
        sc[b][0] = cont[cb + 0]; sc[b][1] = cont[cb + 1]; sc[b][2] = cont[cb + 2];
    }
    __syncthreads();
    size_t base = (size_t)t * G_ * B_;
    for (int idx = tid; idx < G_ * B_; idx += 256) {
        int b = idx & 63;
        int pcol = idx >> 6;
        float4 w = g_cwb[pcol];
        float v = g_bossT[pcol * 64 + sb[b]] + g_heroT[pcol * 200 + sh[b]]
                + sc[b][0] * w.x + sc[b][1] * w.y + sc[b][2] * w.z + w.w;
        g_xg[base + idx] = v;
    }
}

// ---------------- kernel 3: persistent LSTM recurrence ----------------
// grid = 128, block = 256 (8 warps, ksplit-8), smem = 64KB(W) + 128KB(h/partials) + 4KB(g)
__global__ void __launch_bounds__(256, 1) k_recur() {
    extern __shared__ char smem[];
    float2* whs = (float2*)smem;                       // [512][16] duplicated W (64KB)
    char*   hsm = smem + 65536;                        // [512 rows][256B] h slices / partials (128KB)
    float*  gsm = (float*)(smem + 65536 + 131072);     // [16][64] gates (4KB)

    int cta = blockIdx.x, tid = threadIdx.x;
    int w = tid >> 5, lane = tid & 31;
    int bpg = lane & 7, cg = lane >> 3;                // lane tile: 4 cols x 4 bpairs

    // one-time: stage W_h slice
    const float2* wsrc = g_whdup + (size_t)cta * H_ * CPC;
    for (int i = tid; i < H_ * CPC; i += 256) whs[i] = wsrc[i];

    // reduction roles: thread handles 2 gate-ull entries (col, bp, bp+1)
    int rcol  = tid >> 4;            // 0..15
    int rbpg  = (tid >> 1) & 7;
    int rhalf = tid & 1;
    int rbp   = rbpg * 4 + rhalf * 2;
    int rlane = (rcol >> 2) * 8 + rbpg;
    int rapair = (rcol & 3) * 2 + rhalf;

    // gate roles
    int jj = tid >> 6, bb = tid & 63;
    int hc = cta * 4 + jj;
    int pb = permb(bb);
    float c_state = 0.f;

    uint32_t hsm_s = (uint32_t)__cvta_generic_to_shared(hsm);
    uint32_t myslice = hsm_s + w * 16384;
    __syncthreads();

    for (int t = 0; t < T_; ++t) {
        // -------- async-load own 16KB k-slice, 4 pipelined groups of 4KB --------
        const char* src = (const char*)g_hbuf[t & 1] + w * 16384;
        #pragma unroll
        for (int g = 0; g < 4; ++g) {
            #pragma unroll
            for (int i = 0; i < 8; ++i) {
                int off = g * 4096 + i * 512 + lane * 16;
                cp16(myslice + off, src + off);
            }
            cpcommit();
        }

        // xg prefetch (streamed from DRAM, consumed in reduction)
        size_t xoff = ((size_t)t * G_ + cta * CPC + rcol) * B_ + rbp * 2;
        float4 xv = __ldcs((const float4*)(g_xg + xoff));

        ull acc[16];
        #pragma unroll
        for (int a = 0; a < 16; ++a) acc[a] = 0ull;

        const char* hp = hsm + w * 16384 + bpg * 16;
        const char* wp = (const char*)whs + (w * 64) * 128 + cg * 32;

        // -------- GEMM over own 64-k slice --------
        #pragma unroll
        for (int g = 0; g < 4; ++g) {
            if      (g == 0) cpwait<3>();
            else if (g == 1) cpwait<2>();
            else if (g == 2) cpwait<1>();
            else             cpwait<0>();
            __syncwarp();
            #pragma unroll 4
            for (int kk = 0; kk < 16; ++kk) {
                ulonglong2 h01 = *(const ulonglong2*)(hp);        // bpairs 0,1 of tile
                ulonglong2 h23 = *(const ulonglong2*)(hp + 128);  // bpairs 2,3
                ulonglong2 w01 = *(const ulonglong2*)(wp);        // dup cols 0,1
                ulonglong2 w23 = *(const ulonglong2*)(wp + 16);   // dup cols 2,3
                fma2(acc[0],  h01.x, w01.x); fma2(acc[1],  h01.y, w01.x);
                fma2(acc[2],  h23.x, w01.x); fma2(acc[3],  h23.y, w01.x);
                fma2(acc[4],  h01.x, w01.y); fma2(acc[5],  h01.y, w01.y);
                fma2(acc[6],  h23.x, w01.y); fma2(acc[7],  h23.y, w01.y);
                fma2(acc[8],  h01.x, w23.x); fma2(acc[9],  h01.y, w23.x);
                fma2(acc[10], h23.x, w23.x); fma2(acc[11], h23.y, w23.x);
                fma2(acc[12], h01.x, w23.y); fma2(acc[13], h01.y, w23.y);
                fma2(acc[14], h23.x, w23.y); fma2(acc[15], h23.y, w23.y);
                hp += 256; wp += 128;
            }
        }
        // acc[a]: a = ci*4 + bpi -> (col cg*4+ci, bpair bpg*4+bpi), packed {b even, b odd}

        // -------- store partials into own slice (done reading it) --------
        #pragma unroll
        for (int ap = 0; ap < 8; ++ap) {
            *(ulonglong2*)(hsm + w * 16384 + ap * 512 + lane * 16) =
                make_ulonglong2(acc[2 * ap], acc[2 * ap + 1]);
        }
        __syncthreads();

        // -------- ksplit reduction (+ xg) -> gsm --------
        {
            ull s0 = 0ull, s1 = 0ull;
            #pragma unroll
            for (int ww = 0; ww < 8; ++ww) {
                ulonglong2 p = *(const ulonglong2*)(hsm + ww * 16384 + rapair * 512 + rlane * 16);
                add2(s0, p.x); add2(s1, p.y);
            }
            add2(s0, pk2(xv.x, xv.y));
            add2(s1, pk2(xv.z, xv.w));
            float2 f0 = upk(s0), f1 = upk(s1);
            *(float4*)&gsm[rcol * 64 + rbp * 2] = make_float4(f0.x, f0.y, f1.x, f1.y);
        }
        __syncthreads();

        // -------- gates + state update --------
        float gi = gsm[(0 * 4 + jj) * B_ + bb];
        float gf = gsm[(1 * 4 + jj) * B_ + bb];
        float gg = gsm[(2 * 4 + jj) * B_ + bb];
        float go = gsm[(3 * 4 + jj) * B_ + bb];
        float iv = sigf(gi), fv = sigf(gf), gv = tanhf(gg), ov = sigf(go);
        c_state = fv * c_state + iv * gv;
        float h = ov * tanhf(c_state);
        g_hbuf[(t + 1) & 1][hc * B_ + pb] = h;                       // permuted for next step
        g_hs[(size_t)t * (H_ * B_) + hc * B_ + bb] = h;              // natural for MLP

        // -------- grid barrier --------
        __threadfence();
        __syncthreads();
        if (tid == 0) {
            atomicAdd(&g_bar, 1u);
            unsigned tgt = (unsigned)NCTA * (unsigned)(t + 1);
            while (*(volatile unsigned*)&g_bar < tgt) { }
            __threadfence();
        }
        __syncthreads();
    }
}

// ---------------- kernel 4: MLP epilogue ----------------
__global__ void __launch_bounds__(256, 1) k_mlp(const float* __restrict__ W1,
                                                const float* __restrict__ b1,
                                                const float* __restrict__ W2,
                                                const float* __restrict__ b2,
                                                float* __restrict__ out) {
    extern __shared__ char smem[];
    float* hsm = (float*)smem;                          // [512][64] 128KB
    float* w1c = (float*)(smem + 131072);               // [64][256] 64KB
    float* b1s = (float*)(smem + 131072 + 65536);       // 256
    float* w2s = b1s + 256;                             // 256
    float* red = w2s + 256;                             // [16][64]

    int t = blockIdx.x, tid = threadIdx.x;

    const float4* hsrc = (const float4*)(g_hs + (size_t)t * (H_ * B_));
    float4* hd = (float4*)hsm;
    for (int i = tid; i < H_ * B_ / 4; i += 256) hd[i] = hsrc[i];
    b1s[tid] = b1[tid];
    w2s[tid] = W2[tid];
    __syncthreads();

    int bt = tid & 15, mt = tid >> 4;
    int b0 = bt * 4, m0 = mt * 16;

    ull acc[16][2];
    #pragma unroll
    for (int m = 0; m < 16; ++m) {
        float bv = b1s[m0 + m];
        acc[m][0] = pk2(bv, bv);
        acc[m][1] = pk2(bv, bv);
    }

    for (int kc = 0; kc < 8; ++kc) {
        if (kc > 0) __syncthreads();
        const float4* wsrc = (const float4*)(W1 + (size_t)kc * 64 * 256);
        for (int i = tid; i < 4096; i += 256) ((float4*)w1c)[i] = wsrc[i];
        __syncthreads();
        #pragma unroll 4
        for (int k = 0; k < 64; ++k) {
            const ull* hp = (const ull*)&hsm[(kc * 64 + k) * B_ + b0];
            ull h01 = hp[0], h23 = hp[1];
            const float* wr = &w1c[k * 256 + m0];
            #pragma unroll
            for (int m4 = 0; m4 < 4; ++m4) {
                float4 wv = *(const float4*)&wr[m4 * 4];
                ull wa = pk2(wv.x, wv.x), wb = pk2(wv.y, wv.y);
                ull wc = pk2(wv.z, wv.z), wd = pk2(wv.w, wv.w);
                fma2(acc[m4 * 4 + 0][0], h01, wa); fma2(acc[m4 * 4 + 0][1], h23, wa);
                fma2(acc[m4 * 4 + 1][0], h01, wb); fma2(acc[m4 * 4 + 1][1], h23, wb);
                fma2(acc[m4 * 4 + 2][0], h01, wc); fma2(acc[m4 * 4 + 2][1], h23, wc);
                fma2(acc[m4 * 4 + 3][0], h01, wd); fma2(acc[m4 * 4 + 3][1], h23, wd);
            }
        }
    }

    float p0 = 0.f, p1 = 0.f, p2 = 0.f, p3 = 0.f;
    #pragma unroll
    for (int m = 0; m < 16; ++m) {
        float2 v0 = upk(acc[m][0]), v1 = upk(acc[m][1]);
        float wv = w2s[m0 + m];
        p0 += fmaxf(v0.x, 0.f) * wv;
        p1 += fmaxf(v0.y, 0.f) * wv;
        p2 += fmaxf(v1.x, 0.f) * wv;
        p3 += fmaxf(v1.y, 0.f) * wv;
    }
    red[mt * B_ + b0 + 0] = p0;
    red[mt * B_ + b0 + 1] = p1;
    red[mt * B_ + b0 + 2] = p2;
    red[mt * B_ + b0 + 3] = p3;
    __syncthreads();
    if (tid < B_) {
        float s = b2[0];
        #pragma unroll
        for (int q = 0; q < 16; ++q) s += red[q * B_ + tid];
        out[(size_t)tid * T_ + t] = s;
    }
}

// ---------------- launch ----------------
extern "C" void kernel_launch(void* const* d_in, const int* in_sizes, int n_in,
                              void* d_out, int out_size) {
    const int*   boss_anim  = (const int*)d_in[0];
    const int*   hero_anim  = (const int*)d_in[1];
    const float* continuous = (const float*)d_in[2];
    const float* boss_table = (const float*)d_in[3];
    const float* hero_table = (const float*)d_in[4];
    const float* W_i        = (const float*)d_in[5];
    const float* W_h        = (const float*)d_in[6];
    const float* b_lstm     = (const float*)d_in[7];
    const float* W1         = (const float*)d_in[8];
    const float* b1         = (const float*)d_in[9];
    const float* W2         = (const float*)d_in[10];
    const float* b2         = (const float*)d_in[11];
    float* out = (float*)d_out;

    static bool attr_done = false;
    if (!attr_done) {
        cudaFuncSetAttribute(k_recur, cudaFuncAttributeMaxDynamicSharedMemorySize, 65536 + 131072 + 4096);
        cudaFuncSetAttribute(k_mlp,   cudaFuncAttributeMaxDynamicSharedMemorySize, 131072 + 65536 + 2048 + 4096);
        attr_done = true;
    }

    k_init<<<32, 256>>>();
    k_prep<<<G_, 256>>>(boss_table, hero_table, W_i, W_h, b_lstm);
    k_xg<<<T_, 256>>>(boss_anim, hero_anim, continuous);
    k_recur<<<NCTA, 256, 65536 + 131072 + 4096>>>();
    k_mlp<<<T_, 256, 131072 + 65536 + 2048 + 4096>>>(W1, b1, W2, b2, out);
}